// round 16
// baseline (speedup 1.0000x reference)
#include <cuda_runtime.h>

#define NNODES 100000
#define NEDGES 1600000
#define NB_SCAN ((NNODES + 1023) / 1024)
#define NPB 128           // nodes per block in gemm kernels
#define THREADS 256
#define AGG_THREADS 512
#define AGG_WARPS (AGG_THREADS / 32)
#define AOSTRIDE 260      // sAO row stride in floats (2*NPB + 4)

// ---- device scratch (no allocations allowed) ----
__device__ int            g_cnt[NNODES];
__device__ unsigned short g_tick[NEDGES];   // per-edge insertion ticket (16-bit)
__device__ int            g_rowptr[NNODES + 1];
__device__ int            g_csr[NEDGES];
__device__ float          g_inv[NNODES];
__device__ float          g_h0[NNODES * 64];
__device__ float          g_h1[NNODES * 64];
__device__ float          g_ao[NNODES * 64];   // agg rows (fp32)
__device__ int            g_bsum[NB_SCAN];

union U64 { unsigned long long u; float2 f; };

__device__ __forceinline__ void FMA2(unsigned long long& d,
                                     unsigned long long a,
                                     unsigned long long b) {
    asm("fma.rn.f32x2 %0, %1, %2, %0;" : "+l"(d) : "l"(a), "l"(b));
}

// ---------------- CSR build (R12 spec, 16-bit tickets) ----------------
// g_cnt zeroed by static init on first run and by k_scatter's tail each run.
__global__ void k_count(const int* __restrict__ ei) {
    int e = blockIdx.x * blockDim.x + threadIdx.x;
    if (e == 0) g_rowptr[0] = 0;
    if (e < NEDGES / 4) {
        int4 d = __ldg(&((const int4*)(ei + NEDGES))[e]);
        ushort4 t;
        t.x = (unsigned short)atomicAdd(&g_cnt[d.x], 1);
        t.y = (unsigned short)atomicAdd(&g_cnt[d.y], 1);
        t.z = (unsigned short)atomicAdd(&g_cnt[d.z], 1);
        t.w = (unsigned short)atomicAdd(&g_cnt[d.w], 1);
        ((ushort4*)g_tick)[e] = t;
    }
}

__global__ void k_scan1() {
    __shared__ int warpsum[32];
    int t = threadIdx.x;
    int i = blockIdx.x * 1024 + t;
    int v = (i < NNODES) ? g_cnt[i] : 0;
    if (i < NNODES) g_inv[i] = (v > 0) ? (1.0f / (float)v) : 0.0f;
    int x = v;
    #pragma unroll
    for (int off = 1; off < 32; off <<= 1) {
        int y = __shfl_up_sync(0xffffffffu, x, off);
        if ((t & 31) >= off) x += y;
    }
    if ((t & 31) == 31) warpsum[t >> 5] = x;
    __syncthreads();
    if (t < 32) {
        int w = warpsum[t];
        int xs = w;
        #pragma unroll
        for (int off = 1; off < 32; off <<= 1) {
            int y = __shfl_up_sync(0xffffffffu, xs, off);
            if (t >= off) xs += y;
        }
        warpsum[t] = xs - w;   // exclusive
    }
    __syncthreads();
    int incl = x + warpsum[t >> 5];
    if (i < NNODES) g_rowptr[i + 1] = incl;
    if (t == 1023) g_bsum[blockIdx.x] = incl;
}

__global__ void k_scan3() {
    __shared__ int s[128];
    int t = threadIdx.x;
    if (t < 128) s[t] = (t < NB_SCAN) ? g_bsum[t] : 0;
    __syncthreads();
    for (int off = 1; off < 128; off <<= 1) {
        int x = (t < 128 && t >= off) ? s[t - off] : 0;
        __syncthreads();
        if (t < 128) s[t] += x;
        __syncthreads();
    }
    int i = blockIdx.x * blockDim.x + t;
    if (i < NNODES) {
        int b = i >> 10;
        int off = s[b] - g_bsum[b];            // exclusive block offset
        g_rowptr[i + 1] += off;
    }
}

// atomic-free scatter: slot = rowptr[dst] + ticket. Tail re-zeros g_cnt.
__global__ void k_scatter(const int* __restrict__ ei) {
    int e = blockIdx.x * blockDim.x + threadIdx.x;
    if (e < NNODES / 4) ((int4*)g_cnt)[e] = make_int4(0, 0, 0, 0);
    if (e < NEDGES / 4) {
        int4 s = __ldg(&((const int4*)ei)[e]);
        int4 d = __ldg(&((const int4*)(ei + NEDGES))[e]);
        ushort4 t = __ldg(&((const ushort4*)g_tick)[e]);
        int p0 = __ldg(&g_rowptr[d.x]) + t.x;
        int p1 = __ldg(&g_rowptr[d.y]) + t.y;
        int p2 = __ldg(&g_rowptr[d.z]) + t.z;
        int p3 = __ldg(&g_rowptr[d.w]) + t.w;
        g_csr[p0] = s.x;
        g_csr[p1] = s.y;
        g_csr[p2] = s.z;
        g_csr[p3] = s.w;
    }
}

// ---------------- aggregation: EXACT R12 config (best measured) ----------------
template<int DIN>
__global__ void __launch_bounds__(AGG_THREADS) k_agg(const float* __restrict__ hin) {
    constexpr int SUBW = (DIN == 64) ? 16 : 8;    // lanes per node
    constexpr int NPW  = 32 / SUBW;               // nodes per warp
    constexpr int F4   = DIN / 4;                 // float4 per row

    int w = threadIdx.x >> 5, lane = threadIdx.x & 31;
    int sub = lane / SUBW, sl = lane % SUBW;
    int v = (blockIdx.x * AGG_WARPS + w) * NPW + sub;
    bool valid = v < NNODES;
    int r0 = valid ? g_rowptr[v] : 0;
    int r1 = valid ? g_rowptr[v + 1] : 0;
    int last = max(r1 - 1, 0);
    float invv = valid ? g_inv[v] : 0.f;

    const float4* h4 = (const float4*)hin;
    unsigned long long acc0 = 0ull, acc1 = 0ull;
    int i = r0;
    while (__any_sync(0xffffffffu, i < r1)) {
        int s0 = __ldg(&g_csr[min(i,     last)]);
        int s1 = __ldg(&g_csr[min(i + 1, last)]);
        int s2 = __ldg(&g_csr[min(i + 2, last)]);
        int s3 = __ldg(&g_csr[min(i + 3, last)]);
        float4 g0 = __ldg(&h4[s0 * F4 + sl]);
        float4 g1 = __ldg(&h4[s1 * F4 + sl]);
        float4 g2 = __ldg(&h4[s2 * F4 + sl]);
        float4 g3 = __ldg(&h4[s3 * F4 + sl]);
        float m0 = (i     < r1) ? 1.f : 0.f;
        float m1 = (i + 1 < r1) ? 1.f : 0.f;
        float m2 = (i + 2 < r1) ? 1.f : 0.f;
        float m3 = (i + 3 < r1) ? 1.f : 0.f;
        U64 mm0, mm1, mm2, mm3;
        mm0.f = make_float2(m0, m0); mm1.f = make_float2(m1, m1);
        mm2.f = make_float2(m2, m2); mm3.f = make_float2(m3, m3);
        U64 a, b;
        a.f = make_float2(g0.x, g0.y); b.f = make_float2(g0.z, g0.w);
        FMA2(acc0, a.u, mm0.u); FMA2(acc1, b.u, mm0.u);
        a.f = make_float2(g1.x, g1.y); b.f = make_float2(g1.z, g1.w);
        FMA2(acc0, a.u, mm1.u); FMA2(acc1, b.u, mm1.u);
        a.f = make_float2(g2.x, g2.y); b.f = make_float2(g2.z, g2.w);
        FMA2(acc0, a.u, mm2.u); FMA2(acc1, b.u, mm2.u);
        a.f = make_float2(g3.x, g3.y); b.f = make_float2(g3.z, g3.w);
        FMA2(acc0, a.u, mm3.u); FMA2(acc1, b.u, mm3.u);
        i += 4;
    }
    if (valid) {
        U64 u0, u1; u0.u = acc0; u1.u = acc1;
        ((float4*)g_ao)[v * F4 + sl] =
            make_float4(u0.f.x * invv, u0.f.y * invv, u1.f.x * invv, u1.f.y * invv);
    }
}

// ---------------- staging: 128-node tile -> interleaved smem ----------------
// sAO[k][2*vloc + {0,1}] = {agg,own}; row stride AOSTRIDE; 2 threads per node
template<int DIN>
__device__ __forceinline__ void stage_ao(float* sAO, const float* __restrict__ own,
                                         int vbase, int t) {
    int vloc = t >> 1;                    // 0..127
    int v = vbase + vloc;
    bool valid = v < NNODES;
    const float4* a4 = (const float4*)(g_ao + (size_t)v * DIN);
    const float4* o4 = (const float4*)(own + (size_t)v * DIN);
    #pragma unroll
    for (int r = 0; r < DIN / 8; r++) {
        int q = (t & 1) + 2 * r;          // float4 index within row (DIN/4 total)
        float4 a = valid ? __ldg(&a4[q]) : make_float4(0.f, 0.f, 0.f, 0.f);
        float4 o = valid ? __ldg(&o4[q]) : make_float4(0.f, 0.f, 0.f, 0.f);
        int k = 4 * q;
        *(float2*)&sAO[(k + 0) * AOSTRIDE + 2 * vloc] = make_float2(a.x, o.x);
        *(float2*)&sAO[(k + 1) * AOSTRIDE + 2 * vloc] = make_float2(a.y, o.y);
        *(float2*)&sAO[(k + 2) * AOSTRIDE + 2 * vloc] = make_float2(a.z, o.z);
        *(float2*)&sAO[(k + 3) * AOSTRIDE + 2 * vloc] = make_float2(a.w, o.w);
    }
}

// ---------------- GEMM: [agg|own] @ [Wn;Wr] + bn (+relu), 4 nodes x 8 cols/thread ----------------
template<int DIN, bool RELU>
__global__ void __launch_bounds__(THREADS) k_gemm(float* __restrict__ hout,
                                                  const float* __restrict__ own,
                                                  const float* __restrict__ Wn,
                                                  const float* __restrict__ bn,
                                                  const float* __restrict__ Wr) {
    extern __shared__ float smem[];
    float* sW  = smem;                         // DIN*128
    float* sAO = smem + DIN * 128;             // DIN*AOSTRIDE
    float* sb  = sAO + DIN * AOSTRIDE;         // 192

    int t = threadIdx.x;
    for (int i = t; i < DIN * 64; i += THREADS) {
        int k = i >> 6, c = i & 63;
        sW[(k << 7) + 2 * c]     = Wn[i];
        sW[(k << 7) + 2 * c + 1] = Wr[i];
    }
    if (t < 64) sb[t] = bn[t];

    int vbase = blockIdx.x * NPB;
    stage_ao<DIN>(sAO, own, vbase, t);
    __syncthreads();

    int cg = t & 7, ng = t >> 3;               // 8 col-groups x 32 node-groups
    unsigned long long acc[4][8];
    #pragma unroll
    for (int j = 0; j < 4; j++)
        #pragma unroll
        for (int c = 0; c < 8; c++) acc[j][c] = 0ull;

    #pragma unroll 4
    for (int k = 0; k < DIN; k++) {
        const float* wrow = &sW[(k << 7) + (cg << 4)];        // 16 floats = 8 {wn,wr} pairs
        ulonglong2 w0 = *(const ulonglong2*)wrow;
        ulonglong2 w1 = *(const ulonglong2*)(wrow + 4);
        ulonglong2 w2 = *(const ulonglong2*)(wrow + 8);
        ulonglong2 w3 = *(const ulonglong2*)(wrow + 12);
        const float* arow = &sAO[k * AOSTRIDE + (ng << 3)];   // 8 floats = 4 {a,h} pairs
        ulonglong2 a0 = *(const ulonglong2*)arow;
        ulonglong2 a1 = *(const ulonglong2*)(arow + 4);
        unsigned long long ahv[4] = {a0.x, a0.y, a1.x, a1.y};
        unsigned long long wv[8]  = {w0.x, w0.y, w1.x, w1.y, w2.x, w2.y, w3.x, w3.y};
        #pragma unroll
        for (int j = 0; j < 4; j++)
            #pragma unroll
            for (int c = 0; c < 8; c++) FMA2(acc[j][c], ahv[j], wv[c]);
    }

    #pragma unroll
    for (int j = 0; j < 4; j++) {
        int v = vbase + 4 * ng + j;
        if (v < NNODES) {
            float r[8];
            #pragma unroll
            for (int c = 0; c < 8; c++) {
                U64 u; u.u = acc[j][c];
                float val = u.f.x + u.f.y + sb[8 * cg + c];
                r[c] = RELU ? fmaxf(val, 0.f) : val;
            }
            float4 o0; o0.x = r[0]; o0.y = r[1]; o0.z = r[2]; o0.w = r[3];
            float4 o1; o1.x = r[4]; o1.y = r[5]; o1.z = r[6]; o1.w = r[7];
            ((float4*)hout)[v * 16 + 2 * cg]     = o0;
            ((float4*)hout)[v * 16 + 2 * cg + 1] = o1;
        }
    }
}

// ---------------- last GEMM + predictor MLP fused (same tile shape) ----------------
__global__ void __launch_bounds__(THREADS) k_gemm_pred(float* __restrict__ out,
                                                       const float* __restrict__ own,
                                                       const float* __restrict__ Wn,
                                                       const float* __restrict__ bn,
                                                       const float* __restrict__ Wr,
                                                       const float* __restrict__ Wp1,
                                                       const float* __restrict__ bp1,
                                                       const float* __restrict__ Wp2,
                                                       const float* __restrict__ bp2) {
    extern __shared__ float smem[];
    float* sW  = smem;                         // 64*128
    float* sAO = smem + 64 * 128;              // 64*AOSTRIDE
    float* sb  = sAO + 64 * AOSTRIDE;          // 192

    int t = threadIdx.x;
    for (int i = t; i < 4096; i += THREADS) {
        int k = i >> 6, c = i & 63;
        sW[(k << 7) + 2 * c]     = Wn[i];
        sW[(k << 7) + 2 * c + 1] = Wr[i];
    }
    if (t < 64) sb[t] = bn[t];
    float bp2v = __ldg(bp2);

    int vbase = blockIdx.x * NPB;
    stage_ao<64>(sAO, own, vbase, t);
    __syncthreads();

    int cg = t & 7, ng = t >> 3;
    unsigned long long acc[4][8];
    #pragma unroll
    for (int j = 0; j < 4; j++)
        #pragma unroll
        for (int c = 0; c < 8; c++) acc[j][c] = 0ull;

    #pragma unroll 4
    for (int k = 0; k < 64; k++) {
        const float* wrow = &sW[(k << 7) + (cg << 4)];
        ulonglong2 w0 = *(const ulonglong2*)wrow;
        ulonglong2 w1 = *(const ulonglong2*)(wrow + 4);
        ulonglong2 w2 = *(const ulonglong2*)(wrow + 8);
        ulonglong2 w3 = *(const ulonglong2*)(wrow + 12);
        const float* arow = &sAO[k * AOSTRIDE + (ng << 3)];
        ulonglong2 a0 = *(const ulonglong2*)arow;
        ulonglong2 a1 = *(const ulonglong2*)(arow + 4);
        unsigned long long ahv[4] = {a0.x, a0.y, a1.x, a1.y};
        unsigned long long wv[8]  = {w0.x, w0.y, w1.x, w1.y, w2.x, w2.y, w3.x, w3.y};
        #pragma unroll
        for (int j = 0; j < 4; j++)
            #pragma unroll
            for (int c = 0; c < 8; c++) FMA2(acc[j][c], ahv[j], wv[c]);
    }

    // finalize h (no relu), stage into sH (reuse sAO region; 128 nodes x 64 cols = 32K floats)
    float hv[4][8];
    #pragma unroll
    for (int j = 0; j < 4; j++)
        #pragma unroll
        for (int c = 0; c < 8; c++) {
            U64 u; u.u = acc[j][c];
            hv[j][c] = u.f.x + u.f.y + sb[8 * cg + c];
        }
    __syncthreads();                 // all reads of sAO/sW/sb done
    float* sH = sAO;                 // [128 nodes][64 cols]
    #pragma unroll
    for (int j = 0; j < 4; j++) {
        float4 o0; o0.x = hv[j][0]; o0.y = hv[j][1]; o0.z = hv[j][2]; o0.w = hv[j][3];
        float4 o1; o1.x = hv[j][4]; o1.y = hv[j][5]; o1.z = hv[j][6]; o1.w = hv[j][7];
        *(float4*)&sH[(4 * ng + j) * 64 + 8 * cg]     = o0;
        *(float4*)&sH[(4 * ng + j) * 64 + 8 * cg + 4] = o1;
    }
    // reload weights for predictor
    for (int i = t; i < 4096; i += THREADS) sW[i] = Wp1[i];
    if (t < 64) { sb[t] = bp1[t]; sb[64 + t] = Wp2[t]; }
    __syncthreads();

    float pa[4][8];
    #pragma unroll
    for (int j = 0; j < 4; j++)
        #pragma unroll
        for (int c = 0; c < 8; c++) pa[j][c] = sb[8 * cg + c];

    #pragma unroll 4
    for (int k = 0; k < 64; k++) {
        float4 wv0 = *(const float4*)&sW[k * 64 + 8 * cg];
        float4 wv1 = *(const float4*)&sW[k * 64 + 8 * cg + 4];
        #pragma unroll
        for (int j = 0; j < 4; j++) {
            float hk = sH[(4 * ng + j) * 64 + k];
            pa[j][0] += hk * wv0.x; pa[j][1] += hk * wv0.y;
            pa[j][2] += hk * wv0.z; pa[j][3] += hk * wv0.w;
            pa[j][4] += hk * wv1.x; pa[j][5] += hk * wv1.y;
            pa[j][6] += hk * wv1.z; pa[j][7] += hk * wv1.w;
        }
    }

    float4 w20 = *(const float4*)&sb[64 + 8 * cg];
    float4 w21 = *(const float4*)&sb[64 + 8 * cg + 4];
    #pragma unroll
    for (int j = 0; j < 4; j++) {
        float val = fmaxf(pa[j][0], 0.f) * w20.x + fmaxf(pa[j][1], 0.f) * w20.y
                  + fmaxf(pa[j][2], 0.f) * w20.z + fmaxf(pa[j][3], 0.f) * w20.w
                  + fmaxf(pa[j][4], 0.f) * w21.x + fmaxf(pa[j][5], 0.f) * w21.y
                  + fmaxf(pa[j][6], 0.f) * w21.z + fmaxf(pa[j][7], 0.f) * w21.w;
        // reduce over the 8 cg lanes (consecutive lanes within the warp)
        #pragma unroll
        for (int off = 1; off < 8; off <<= 1)
            val += __shfl_xor_sync(0xffffffffu, val, off);
        if (cg == 0) {
            int v = vbase + 4 * ng + j;
            if (v < NNODES) out[v] = 1.0f / (1.0f + __expf(-(val + bp2v)));
        }
    }
}

// ---------------- launch ----------------
extern "C" void kernel_launch(void* const* d_in, const int* in_sizes, int n_in,
                              void* d_out, int out_size) {
    const float* x   = (const float*)d_in[0];
    const int*   ei  = (const int*)d_in[1];
    const float* Wn0 = (const float*)d_in[2];
    const float* bn0 = (const float*)d_in[3];
    const float* Wr0 = (const float*)d_in[4];
    const float* Wn1 = (const float*)d_in[5];
    const float* bn1 = (const float*)d_in[6];
    const float* Wr1 = (const float*)d_in[7];
    const float* Wn2 = (const float*)d_in[8];
    const float* bn2 = (const float*)d_in[9];
    const float* Wr2 = (const float*)d_in[10];
    const float* Wp1 = (const float*)d_in[11];
    const float* bp1 = (const float*)d_in[12];
    const float* Wp2 = (const float*)d_in[13];
    const float* bp2 = (const float*)d_in[14];
    float* out = (float*)d_out;

    float *h0 = 0, *h1 = 0;
    cudaGetSymbolAddress((void**)&h0, g_h0);
    cudaGetSymbolAddress((void**)&h1, g_h1);

    const int smem32 = (32 * 128 + 32 * AOSTRIDE + 192) * 4;   // 50432
    const int smem64 = (64 * 128 + 64 * AOSTRIDE + 192) * 4;   // 100096
    cudaFuncSetAttribute(k_gemm<32, true>, cudaFuncAttributeMaxDynamicSharedMemorySize, smem32);
    cudaFuncSetAttribute(k_gemm<64, true>, cudaFuncAttributeMaxDynamicSharedMemorySize, smem64);
    cudaFuncSetAttribute(k_gemm_pred,      cudaFuncAttributeMaxDynamicSharedMemorySize, smem64);

    int nb_nodes = (NNODES + 255) / 256;
    int nb_e4    = (NEDGES / 4 + 255) / 256;
    int nb_agg64 = (NNODES + AGG_WARPS * 2 - 1) / (AGG_WARPS * 2);   // 2 nodes/warp
    int nb_agg32 = (NNODES + AGG_WARPS * 4 - 1) / (AGG_WARPS * 4);   // 4 nodes/warp
    int nb_tile  = (NNODES + NPB - 1) / NPB;                         // 782

    // CSR build (R12 spec; launch #4 = k_scatter -> profiled slot)
    k_count  <<<nb_e4, 256>>>(ei);
    k_scan1  <<<NB_SCAN, 1024>>>();
    k_scan3  <<<nb_nodes, 256>>>();
    k_scatter<<<nb_e4, 256>>>(ei);

    // GNN: R12 agg, widened-tile GEMMs (4 nodes x 8 cols per thread)
    k_agg<32><<<nb_agg32, AGG_THREADS>>>(x);
    k_gemm<32, true ><<<nb_tile, THREADS, smem32>>>(h0, x,  Wn0, bn0, Wr0);
    k_agg<64><<<nb_agg64, AGG_THREADS>>>(h0);
    k_gemm<64, true ><<<nb_tile, THREADS, smem64>>>(h1, h0, Wn1, bn1, Wr1);
    k_agg<64><<<nb_agg64, AGG_THREADS>>>(h1);
    k_gemm_pred      <<<nb_tile, THREADS, smem64>>>(out, h1, Wn2, bn2, Wr2,
                                                    Wp1, bp1, Wp2, bp2);
}

// round 17
// speedup vs baseline: 1.4674x; 1.4674x over previous
#include <cuda_runtime.h>

#define NNODES 100000
#define NEDGES 1600000
#define NB_SCAN ((NNODES + 1023) / 1024)
#define NPB 64            // nodes per block in gemm kernels
#define THREADS 256
#define AGG_THREADS 512
#define AGG_WARPS (AGG_THREADS / 32)

// ---- device scratch (no allocations allowed) ----
__device__ int            g_cnt[NNODES];
__device__ unsigned short g_tick[NEDGES];   // per-edge insertion ticket (16-bit)
__device__ int            g_rowptr[NNODES + 1];
__device__ int            g_csr[NEDGES];
__device__ float          g_inv[NNODES];
__device__ float          g_h0[NNODES * 64];
__device__ float          g_h1[NNODES * 64];
__device__ float          g_ao[NNODES * 64];   // agg rows (fp32)
__device__ int            g_bsum[NB_SCAN];

union U64 { unsigned long long u; float2 f; };

__device__ __forceinline__ void FMA2(unsigned long long& d,
                                     unsigned long long a,
                                     unsigned long long b) {
    asm("fma.rn.f32x2 %0, %1, %2, %0;" : "+l"(d) : "l"(a), "l"(b));
}

// ---------------- CSR build (R12 spec, 16-bit tickets) ----------------
// g_cnt zeroed by static init on first run and by k_scatter's tail each run.
__global__ void k_count(const int* __restrict__ ei) {
    int e = blockIdx.x * blockDim.x + threadIdx.x;
    if (e == 0) g_rowptr[0] = 0;
    if (e < NEDGES / 4) {
        int4 d = __ldg(&((const int4*)(ei + NEDGES))[e]);
        ushort4 t;
        t.x = (unsigned short)atomicAdd(&g_cnt[d.x], 1);
        t.y = (unsigned short)atomicAdd(&g_cnt[d.y], 1);
        t.z = (unsigned short)atomicAdd(&g_cnt[d.z], 1);
        t.w = (unsigned short)atomicAdd(&g_cnt[d.w], 1);
        ((ushort4*)g_tick)[e] = t;
    }
}

__global__ void k_scan1() {
    cudaGridDependencySynchronize();
    __shared__ int warpsum[32];
    int t = threadIdx.x;
    int i = blockIdx.x * 1024 + t;
    int v = (i < NNODES) ? g_cnt[i] : 0;
    if (i < NNODES) g_inv[i] = (v > 0) ? (1.0f / (float)v) : 0.0f;
    int x = v;
    #pragma unroll
    for (int off = 1; off < 32; off <<= 1) {
        int y = __shfl_up_sync(0xffffffffu, x, off);
        if ((t & 31) >= off) x += y;
    }
    if ((t & 31) == 31) warpsum[t >> 5] = x;
    __syncthreads();
    if (t < 32) {
        int w = warpsum[t];
        int xs = w;
        #pragma unroll
        for (int off = 1; off < 32; off <<= 1) {
            int y = __shfl_up_sync(0xffffffffu, xs, off);
            if (t >= off) xs += y;
        }
        warpsum[t] = xs - w;   // exclusive
    }
    __syncthreads();
    int incl = x + warpsum[t >> 5];
    if (i < NNODES) g_rowptr[i + 1] = incl;
    if (t == 1023) g_bsum[blockIdx.x] = incl;
}

__global__ void k_scan3() {
    cudaGridDependencySynchronize();
    __shared__ int s[128];
    int t = threadIdx.x;
    if (t < 128) s[t] = (t < NB_SCAN) ? g_bsum[t] : 0;
    __syncthreads();
    for (int off = 1; off < 128; off <<= 1) {
        int x = (t < 128 && t >= off) ? s[t - off] : 0;
        __syncthreads();
        if (t < 128) s[t] += x;
        __syncthreads();
    }
    int i = blockIdx.x * blockDim.x + t;
    if (i < NNODES) {
        int b = i >> 10;
        int off = s[b] - g_bsum[b];            // exclusive block offset
        g_rowptr[i + 1] += off;
    }
}

// atomic-free scatter: slot = rowptr[dst] + ticket. Tail re-zeros g_cnt.
__global__ void k_scatter(const int* __restrict__ ei) {
    cudaGridDependencySynchronize();
    int e = blockIdx.x * blockDim.x + threadIdx.x;
    if (e < NNODES / 4) ((int4*)g_cnt)[e] = make_int4(0, 0, 0, 0);
    if (e < NEDGES / 4) {
        int4 s = __ldg(&((const int4*)ei)[e]);
        int4 d = __ldg(&((const int4*)(ei + NEDGES))[e]);
        ushort4 t = __ldg(&((const ushort4*)g_tick)[e]);
        int p0 = __ldg(&g_rowptr[d.x]) + t.x;
        int p1 = __ldg(&g_rowptr[d.y]) + t.y;
        int p2 = __ldg(&g_rowptr[d.z]) + t.z;
        int p3 = __ldg(&g_rowptr[d.w]) + t.w;
        g_csr[p0] = s.x;
        g_csr[p1] = s.y;
        g_csr[p2] = s.z;
        g_csr[p3] = s.w;
    }
}

// ---------------- aggregation: EXACT R12 config (best measured) ----------------
template<int DIN>
__global__ void __launch_bounds__(AGG_THREADS) k_agg(const float* __restrict__ hin) {
    cudaGridDependencySynchronize();
    constexpr int SUBW = (DIN == 64) ? 16 : 8;    // lanes per node
    constexpr int NPW  = 32 / SUBW;               // nodes per warp
    constexpr int F4   = DIN / 4;                 // float4 per row

    int w = threadIdx.x >> 5, lane = threadIdx.x & 31;
    int sub = lane / SUBW, sl = lane % SUBW;
    int v = (blockIdx.x * AGG_WARPS + w) * NPW + sub;
    bool valid = v < NNODES;
    int r0 = valid ? g_rowptr[v] : 0;
    int r1 = valid ? g_rowptr[v + 1] : 0;
    int last = max(r1 - 1, 0);
    float invv = valid ? g_inv[v] : 0.f;

    const float4* h4 = (const float4*)hin;
    unsigned long long acc0 = 0ull, acc1 = 0ull;
    int i = r0;
    while (__any_sync(0xffffffffu, i < r1)) {
        int s0 = __ldg(&g_csr[min(i,     last)]);
        int s1 = __ldg(&g_csr[min(i + 1, last)]);
        int s2 = __ldg(&g_csr[min(i + 2, last)]);
        int s3 = __ldg(&g_csr[min(i + 3, last)]);
        float4 g0 = __ldg(&h4[s0 * F4 + sl]);
        float4 g1 = __ldg(&h4[s1 * F4 + sl]);
        float4 g2 = __ldg(&h4[s2 * F4 + sl]);
        float4 g3 = __ldg(&h4[s3 * F4 + sl]);
        float m0 = (i     < r1) ? 1.f : 0.f;
        float m1 = (i + 1 < r1) ? 1.f : 0.f;
        float m2 = (i + 2 < r1) ? 1.f : 0.f;
        float m3 = (i + 3 < r1) ? 1.f : 0.f;
        U64 mm0, mm1, mm2, mm3;
        mm0.f = make_float2(m0, m0); mm1.f = make_float2(m1, m1);
        mm2.f = make_float2(m2, m2); mm3.f = make_float2(m3, m3);
        U64 a, b;
        a.f = make_float2(g0.x, g0.y); b.f = make_float2(g0.z, g0.w);
        FMA2(acc0, a.u, mm0.u); FMA2(acc1, b.u, mm0.u);
        a.f = make_float2(g1.x, g1.y); b.f = make_float2(g1.z, g1.w);
        FMA2(acc0, a.u, mm1.u); FMA2(acc1, b.u, mm1.u);
        a.f = make_float2(g2.x, g2.y); b.f = make_float2(g2.z, g2.w);
        FMA2(acc0, a.u, mm2.u); FMA2(acc1, b.u, mm2.u);
        a.f = make_float2(g3.x, g3.y); b.f = make_float2(g3.z, g3.w);
        FMA2(acc0, a.u, mm3.u); FMA2(acc1, b.u, mm3.u);
        i += 4;
    }
    if (valid) {
        U64 u0, u1; u0.u = acc0; u1.u = acc1;
        ((float4*)g_ao)[v * F4 + sl] =
            make_float4(u0.f.x * invv, u0.f.y * invv, u1.f.x * invv, u1.f.y * invv);
    }
}

// ---------------- staging: agg (g_ao) + own (fp32 h) -> interleaved smem ----------------
// sAO[k][2*vloc + {0,1}] = {agg,own}; row stride 132
template<int DIN>
__device__ __forceinline__ void stage_ao(float* sAO, const float* __restrict__ own,
                                         int vbase, int t) {
    int vloc = t >> 2;
    int v = vbase + vloc;
    bool valid = v < NNODES;
    const float4* a4 = (const float4*)(g_ao + (size_t)v * DIN);
    const float4* o4 = (const float4*)(own + (size_t)v * DIN);
    #pragma unroll
    for (int r = 0; r < DIN / 16; r++) {
        int q = (t & 3) + 4 * r;          // float4 index within row (DIN/4 of them)
        float4 a = valid ? __ldg(&a4[q]) : make_float4(0.f, 0.f, 0.f, 0.f);
        float4 o = valid ? __ldg(&o4[q]) : make_float4(0.f, 0.f, 0.f, 0.f);
        int k = 4 * q;
        *(float2*)&sAO[(k + 0) * 132 + 2 * vloc] = make_float2(a.x, o.x);
        *(float2*)&sAO[(k + 1) * 132 + 2 * vloc] = make_float2(a.y, o.y);
        *(float2*)&sAO[(k + 2) * 132 + 2 * vloc] = make_float2(a.z, o.z);
        *(float2*)&sAO[(k + 3) * 132 + 2 * vloc] = make_float2(a.w, o.w);
    }
}

// ---------------- GEMM: [agg|own] @ [Wn;Wr] + bn (+relu), 4x4 tile (R12) ----------------
// PDL: weights/bias staged BEFORE grid sync (harness inputs, independent of
// predecessor kernels) -> overlaps with agg straggler tail.
template<int DIN, bool RELU>
__global__ void __launch_bounds__(THREADS) k_gemm(float* __restrict__ hout,
                                                  const float* __restrict__ own,
                                                  const float* __restrict__ Wn,
                                                  const float* __restrict__ bn,
                                                  const float* __restrict__ Wr) {
    extern __shared__ float smem[];
    float* sW  = smem;                     // DIN*128
    float* sAO = smem + DIN * 128;         // DIN*132
    float* sb  = sAO + DIN * 132;          // 192

    int t = threadIdx.x;
    for (int i = t; i < DIN * 64; i += THREADS) {
        int k = i >> 6, c = i & 63;
        sW[(k << 7) + 2 * c]     = Wn[i];
        sW[(k << 7) + 2 * c + 1] = Wr[i];
    }
    if (t < 64) sb[t] = bn[t];

    cudaGridDependencySynchronize();       // wait for k_agg's g_ao (and h from prior gemm)

    int vbase = blockIdx.x * NPB;
    stage_ao<DIN>(sAO, own, vbase, t);
    __syncthreads();

    int cg = t & 15, ng = t >> 4;
    unsigned long long acc[4][4];
    #pragma unroll
    for (int j = 0; j < 4; j++)
        #pragma unroll
        for (int c = 0; c < 4; c++) acc[j][c] = 0ull;

    #pragma unroll 8
    for (int k = 0; k < DIN; k++) {
        const float* wrow = &sW[(k << 7) + (cg << 3)];
        ulonglong2 w0 = *(const ulonglong2*)wrow;
        ulonglong2 w1 = *(const ulonglong2*)(wrow + 4);
        const float* arow = &sAO[k * 132 + (ng << 3)];
        ulonglong2 a0 = *(const ulonglong2*)arow;
        ulonglong2 a1 = *(const ulonglong2*)(arow + 4);
        unsigned long long ahv[4] = {a0.x, a0.y, a1.x, a1.y};
        unsigned long long wv[4]  = {w0.x, w0.y, w1.x, w1.y};
        #pragma unroll
        for (int j = 0; j < 4; j++)
            #pragma unroll
            for (int c = 0; c < 4; c++) FMA2(acc[j][c], ahv[j], wv[c]);
    }

    #pragma unroll
    for (int j = 0; j < 4; j++) {
        int v = vbase + 4 * ng + j;
        if (v < NNODES) {
            float r[4];
            #pragma unroll
            for (int c = 0; c < 4; c++) {
                U64 u; u.u = acc[j][c];
                float val = u.f.x + u.f.y + sb[4 * cg + c];
                r[c] = RELU ? fmaxf(val, 0.f) : val;
            }
            float4 o; o.x = r[0]; o.y = r[1]; o.z = r[2]; o.w = r[3];
            ((float4*)hout)[v * 16 + cg] = o;
        }
    }
}

// ---------------- last GEMM + predictor MLP fused (R12) ----------------
__global__ void __launch_bounds__(THREADS) k_gemm_pred(float* __restrict__ out,
                                                       const float* __restrict__ own,
                                                       const float* __restrict__ Wn,
                                                       const float* __restrict__ bn,
                                                       const float* __restrict__ Wr,
                                                       const float* __restrict__ Wp1,
                                                       const float* __restrict__ bp1,
                                                       const float* __restrict__ Wp2,
                                                       const float* __restrict__ bp2) {
    extern __shared__ float smem[];
    float* sW  = smem;                       // 64*128
    float* sAO = smem + 64 * 128;            // 64*132
    float* sb  = smem + 64 * 128 + 64 * 132; // 192

    int t = threadIdx.x;
    for (int i = t; i < 4096; i += THREADS) {
        int k = i >> 6, c = i & 63;
        sW[(k << 7) + 2 * c]     = Wn[i];
        sW[(k << 7) + 2 * c + 1] = Wr[i];
    }
    if (t < 64) sb[t] = bn[t];
    float bp2v = __ldg(bp2);

    cudaGridDependencySynchronize();         // wait for k_agg<64>(h1)

    int vbase = blockIdx.x * NPB;
    stage_ao<64>(sAO, own, vbase, t);
    __syncthreads();

    int cg = t & 15, ng = t >> 4;
    unsigned long long acc[4][4];
    #pragma unroll
    for (int j = 0; j < 4; j++)
        #pragma unroll
        for (int c = 0; c < 4; c++) acc[j][c] = 0ull;

    #pragma unroll 8
    for (int k = 0; k < 64; k++) {
        const float* wrow = &sW[(k << 7) + (cg << 3)];
        ulonglong2 w0 = *(const ulonglong2*)wrow;
        ulonglong2 w1 = *(const ulonglong2*)(wrow + 4);
        const float* arow = &sAO[k * 132 + (ng << 3)];
        ulonglong2 a0 = *(const ulonglong2*)arow;
        ulonglong2 a1 = *(const ulonglong2*)(arow + 4);
        unsigned long long ahv[4] = {a0.x, a0.y, a1.x, a1.y};
        unsigned long long wv[4]  = {w0.x, w0.y, w1.x, w1.y};
        #pragma unroll
        for (int j = 0; j < 4; j++)
            #pragma unroll
            for (int c = 0; c < 4; c++) FMA2(acc[j][c], ahv[j], wv[c]);
    }

    // finalize h (no relu), stage into sH (reuse sAO region)
    float hv[4][4];
    #pragma unroll
    for (int j = 0; j < 4; j++)
        #pragma unroll
        for (int c = 0; c < 4; c++) {
            U64 u; u.u = acc[j][c];
            hv[j][c] = u.f.x + u.f.y + sb[4 * cg + c];
        }
    __syncthreads();                 // all reads of sAO/sW/sb done
    float* sH = sAO;                 // [64 nodes][64 cols]
    #pragma unroll
    for (int j = 0; j < 4; j++) {
        float4 o; o.x = hv[j][0]; o.y = hv[j][1]; o.z = hv[j][2]; o.w = hv[j][3];
        *(float4*)&sH[(4 * ng + j) * 64 + 4 * cg] = o;
    }
    // reload weights for predictor
    for (int i = t; i < 4096; i += THREADS) sW[i] = Wp1[i];
    if (t < 64) { sb[t] = bp1[t]; sb[64 + t] = Wp2[t]; }
    __syncthreads();

    float pa[4][4];
    #pragma unroll
    for (int j = 0; j < 4; j++)
        #pragma unroll
        for (int c = 0; c < 4; c++) pa[j][c] = sb[4 * cg + c];

    #pragma unroll 8
    for (int k = 0; k < 64; k++) {
        float4 wv = *(const float4*)&sW[k * 64 + 4 * cg];
        float h0v = sH[(4 * ng + 0) * 64 + k];
        float h1v = sH[(4 * ng + 1) * 64 + k];
        float h2v = sH[(4 * ng + 2) * 64 + k];
        float h3v = sH[(4 * ng + 3) * 64 + k];
        pa[0][0] += h0v * wv.x; pa[0][1] += h0v * wv.y; pa[0][2] += h0v * wv.z; pa[0][3] += h0v * wv.w;
        pa[1][0] += h1v * wv.x; pa[1][1] += h1v * wv.y; pa[1][2] += h1v * wv.z; pa[1][3] += h1v * wv.w;
        pa[2][0] += h2v * wv.x; pa[2][1] += h2v * wv.y; pa[2][2] += h2v * wv.z; pa[2][3] += h2v * wv.w;
        pa[3][0] += h3v * wv.x; pa[3][1] += h3v * wv.y; pa[3][2] += h3v * wv.z; pa[3][3] += h3v * wv.w;
    }

    float4 w2 = *(const float4*)&sb[64 + 4 * cg];
    #pragma unroll
    for (int j = 0; j < 4; j++) {
        float val = fmaxf(pa[j][0], 0.f) * w2.x + fmaxf(pa[j][1], 0.f) * w2.y
                  + fmaxf(pa[j][2], 0.f) * w2.z + fmaxf(pa[j][3], 0.f) * w2.w;
        #pragma unroll
        for (int off = 1; off < 16; off <<= 1)
            val += __shfl_xor_sync(0xffffffffu, val, off);
        if (cg == 0) {
            int v = vbase + 4 * ng + j;
            if (v < NNODES) out[v] = 1.0f / (1.0f + __expf(-(val + bp2v)));
        }
    }
}

// ---------------- launch (PDL on all dependent kernels) ----------------
template<typename F, typename... Args>
static inline void launch_pdl(F kern, int grid, int block, size_t smem, Args... args) {
    cudaLaunchConfig_t cfg = {};
    cfg.gridDim = dim3(grid, 1, 1);
    cfg.blockDim = dim3(block, 1, 1);
    cfg.dynamicSmemBytes = smem;
    cfg.stream = 0;
    cudaLaunchAttribute attr[1];
    attr[0].id = cudaLaunchAttributeProgrammaticStreamSerialization;
    attr[0].val.programmaticStreamSerializationAllowed = 1;
    cfg.attrs = attr;
    cfg.numAttrs = 1;
    cudaLaunchKernelEx(&cfg, kern, args...);
}

extern "C" void kernel_launch(void* const* d_in, const int* in_sizes, int n_in,
                              void* d_out, int out_size) {
    const float* x   = (const float*)d_in[0];
    const int*   ei  = (const int*)d_in[1];
    const float* Wn0 = (const float*)d_in[2];
    const float* bn0 = (const float*)d_in[3];
    const float* Wr0 = (const float*)d_in[4];
    const float* Wn1 = (const float*)d_in[5];
    const float* bn1 = (const float*)d_in[6];
    const float* Wr1 = (const float*)d_in[7];
    const float* Wn2 = (const float*)d_in[8];
    const float* bn2 = (const float*)d_in[9];
    const float* Wr2 = (const float*)d_in[10];
    const float* Wp1 = (const float*)d_in[11];
    const float* bp1 = (const float*)d_in[12];
    const float* Wp2 = (const float*)d_in[13];
    const float* bp2 = (const float*)d_in[14];
    float* out = (float*)d_out;

    float *h0 = 0, *h1 = 0;
    cudaGetSymbolAddress((void**)&h0, g_h0);
    cudaGetSymbolAddress((void**)&h1, g_h1);

    const int smem32 = (32 * 128 + 32 * 132 + 192) * 4;   // 34048
    const int smem64 = (64 * 128 + 64 * 132 + 192) * 4;   // 67328
    cudaFuncSetAttribute(k_gemm<64, true>, cudaFuncAttributeMaxDynamicSharedMemorySize, smem64);
    cudaFuncSetAttribute(k_gemm_pred,      cudaFuncAttributeMaxDynamicSharedMemorySize, smem64);

    int nb_nodes = (NNODES + 255) / 256;
    int nb_e4    = (NEDGES / 4 + 255) / 256;
    int nb_agg64 = (NNODES + AGG_WARPS * 2 - 1) / (AGG_WARPS * 2);   // 2 nodes/warp
    int nb_agg32 = (NNODES + AGG_WARPS * 4 - 1) / (AGG_WARPS * 4);   // 4 nodes/warp
    int nb_tile  = (NNODES + NPB - 1) / NPB;

    // CSR build (first launch plain; rest PDL-serialized)
    k_count<<<nb_e4, 256>>>(ei);
    launch_pdl(k_scan1,   NB_SCAN, 1024, 0);
    launch_pdl(k_scan3,   nb_nodes, 256, 0);
    launch_pdl(k_scatter, nb_e4, 256, 0, ei);

    // GNN: R12 kernels, PDL-chained
    launch_pdl(k_agg<32>,        nb_agg32, AGG_THREADS, 0, x);
    launch_pdl(k_gemm<32, true>, nb_tile, THREADS, (size_t)smem32, h0, x,  Wn0, bn0, Wr0);
    launch_pdl(k_agg<64>,        nb_agg64, AGG_THREADS, 0, (const float*)h0);
    launch_pdl(k_gemm<64, true>, nb_tile, THREADS, (size_t)smem64, h1, (const float*)h0, Wn1, bn1, Wr1);
    launch_pdl(k_agg<64>,        nb_agg64, AGG_THREADS, 0, (const float*)h1);
    launch_pdl(k_gemm_pred,      nb_tile, THREADS, (size_t)smem64, out, (const float*)h1,
               Wn2, bn2, Wr2, Wp1, bp1, Wp2, bp2);
}